// round 6
// baseline (speedup 1.0000x reference)
#include <cuda_runtime.h>
#include <cstdint>

#define NN 65536
#define DD 512
#define HH 256
#define KK 16
#define LL 3
#define CC 64
#define CK 1024   // C*K

// ---------------- scratch (device globals; no allocations allowed) ----------------
__device__ float g_current[NN * DD];     // updated features
__device__ int   g_seg[NN];
__device__ int   g_cnt[CK];
__device__ int   g_off[CK];
__device__ int   g_cur[CK];
__device__ int   g_order[NN];
__device__ float g_means[CK * DD];
__device__ float g_h[CK * DD];
__device__ float g_ref[CK * DD];
__device__ float g_lp[CC * DD];
__device__ float g_comb[CC * LL * DD];
__device__ float g_t[CC * DD];

// ---------------- packed f32x2 helpers ----------------
__device__ __forceinline__ unsigned long long fma2(unsigned long long a,
                                                   unsigned long long b,
                                                   unsigned long long c) {
    unsigned long long d;
    asm("fma.rn.f32x2 %0, %1, %2, %3;" : "=l"(d) : "l"(a), "l"(b), "l"(c));
    return d;
}
__device__ __forceinline__ unsigned long long pack2(float v) {
    unsigned long long r;
    asm("mov.b64 %0, {%1, %1};" : "=l"(r) : "f"(v));
    return r;
}
__device__ __forceinline__ float2 unpack2(unsigned long long v) {
    float2 r;
    asm("mov.b64 {%0, %1}, %2;" : "=f"(r.x), "=f"(r.y) : "l"(v));
    return r;
}

// ---------------- cp.async helpers ----------------
__device__ __forceinline__ unsigned smem_u32(const void* p) {
    return (unsigned)__cvta_generic_to_shared(p);
}
__device__ __forceinline__ void cp16(unsigned dst, const void* src) {
    asm volatile("cp.async.cg.shared.global [%0], [%1], 16;\n" :: "r"(dst), "l"(src));
}
__device__ __forceinline__ void cp_commit() {
    asm volatile("cp.async.commit_group;\n");
}
__device__ __forceinline__ void cp_wait1() {
    asm volatile("cp.async.wait_group 1;\n");
}

// ---------------- kernel 1: fused hidden GEMM + logits + argmax -> seg ----------------
// BM=64 rows, BN=256 (=H) cols, BK=16, 3-stage cp.async pipeline.
// 256 threads: warp w owns rows w*8..w*8+7, lane l owns cols l*8..l*8+7.
#define ST 3
__launch_bounds__(256, 2)
__global__ void assign_kernel(const float* __restrict__ X,
                              const float* __restrict__ W1,   // [512,256]
                              const float* __restrict__ B1,   // [256]
                              const float* __restrict__ W2,   // [256,16]
                              const float* __restrict__ B2,   // [16]
                              const int*   __restrict__ labels)
{
    __shared__ float As[ST][64][16];    // row-major: A frag read is warp-broadcast
    __shared__ float Bs[ST][16][256];
    const int tid  = threadIdx.x;
    const int warp = tid >> 5, lane = tid & 31;
    const int row0 = blockIdx.x * 64;

    // cp.async source/dest coordinates
    const int arow = tid >> 2, ac4 = (tid & 3) << 2;                 // A: 64x16 = 256 x 16B
    const float* Asrc = X + (size_t)(row0 + arow) * DD + ac4;
    // B: 16x256 floats = 1024 x 16B chunks, 4 per thread
    const float* Bbase = W1;

    unsigned long long acc[8][4];
#pragma unroll
    for (int r = 0; r < 8; r++)
#pragma unroll
        for (int p = 0; p < 4; p++) acc[r][p] = 0ull;

    // prologue: issue stages 0 and 1
#pragma unroll
    for (int s = 0; s < 2; s++) {
        const int k0 = s * 16;
        cp16(smem_u32(&As[s][arow][ac4]), Asrc + k0);
#pragma unroll
        for (int i = 0; i < 4; i++) {
            int id = tid + i * 256;
            int br = id >> 6, bc = (id & 63) << 2;
            cp16(smem_u32(&Bs[s][br][bc]), Bbase + (size_t)(k0 + br) * HH + bc);
        }
        cp_commit();
    }

    const int NIT = DD / 16;   // 32
    int s = 0;
    for (int it = 0; it < NIT; it++) {
        cp_wait1();
        __syncthreads();

        // issue stage it+2 (writes stage (it+2)%ST == (it-1)%ST, already past sync)
        if (it + 2 < NIT) {
            const int sn = (it + 2) % ST;
            const int k0 = (it + 2) * 16;
            cp16(smem_u32(&As[sn][arow][ac4]), Asrc + k0);
#pragma unroll
            for (int i = 0; i < 4; i++) {
                int id = tid + i * 256;
                int br = id >> 6, bc = (id & 63) << 2;
                cp16(smem_u32(&Bs[sn][br][bc]), Bbase + (size_t)(k0 + br) * HH + bc);
            }
        }
        cp_commit();   // unconditional so wait_group 1 always covers current stage

        // compute on stage s
#pragma unroll
        for (int kq = 0; kq < 4; kq++) {          // 4 k-steps of 4
            float4 a4[8];
#pragma unroll
            for (int r = 0; r < 8; r++)           // broadcast LDS.128
                a4[r] = *(const float4*)&As[s][warp * 8 + r][kq * 4];
#pragma unroll
            for (int ki = 0; ki < 4; ki++) {
                const int kk = kq * 4 + ki;
                const ulonglong2* bp = (const ulonglong2*)&Bs[s][kk][lane * 8];
                ulonglong2 b01 = bp[0], b23 = bp[1];
#pragma unroll
                for (int r = 0; r < 8; r++) {
                    float av = (ki == 0) ? a4[r].x : (ki == 1) ? a4[r].y
                             : (ki == 2) ? a4[r].z : a4[r].w;
                    unsigned long long a2 = pack2(av);
                    acc[r][0] = fma2(a2, b01.x, acc[r][0]);
                    acc[r][1] = fma2(a2, b01.y, acc[r][1]);
                    acc[r][2] = fma2(a2, b23.x, acc[r][2]);
                    acc[r][3] = fma2(a2, b23.y, acc[r][3]);
                }
            }
        }
        s = (s + 1) % ST;
    }

    // epilogue: bias + relu -> hidden
    float h[8][8];
    {
        float bb[8];
#pragma unroll
        for (int c = 0; c < 8; c++) bb[c] = B1[lane * 8 + c];
#pragma unroll
        for (int r = 0; r < 8; r++)
#pragma unroll
            for (int p = 0; p < 4; p++) {
                float2 v = unpack2(acc[r][p]);
                h[r][2 * p]     = fmaxf(v.x + bb[2 * p], 0.f);
                h[r][2 * p + 1] = fmaxf(v.y + bb[2 * p + 1], 0.f);
            }
    }

    // logits + argmax (first-max tie-break like jnp.argmax)
    float best[8]; int bi[8];
#pragma unroll
    for (int r = 0; r < 8; r++) { best[r] = -3.402823466e38f; bi[r] = 0; }
    const float* W2p = W2 + (size_t)(lane * 8) * KK;
    for (int j = 0; j < KK; j++) {
        float w2c[8];
#pragma unroll
        for (int c = 0; c < 8; c++) w2c[c] = W2p[c * KK + j];
        float pj[8];
#pragma unroll
        for (int r = 0; r < 8; r++) {
            float sv = 0.f;
#pragma unroll
            for (int c = 0; c < 8; c++) sv += h[r][c] * w2c[c];
            pj[r] = sv;
        }
#pragma unroll
        for (int o = 16; o > 0; o >>= 1) {
#pragma unroll
            for (int r = 0; r < 8; r++)
                pj[r] += __shfl_xor_sync(0xffffffffu, pj[r], o);
        }
        float bj = B2[j];
#pragma unroll
        for (int r = 0; r < 8; r++) {
            float v = pj[r] + bj;
            if (v > best[r]) { best[r] = v; bi[r] = j; }
        }
    }
    if (lane < 8) {
        int row = row0 + warp * 8 + lane;
        g_seg[row] = labels[row] * KK + bi[lane];
    }
}

// ---------------- segment machinery (counting sort) ----------------
__global__ void zero_cnt_kernel() { g_cnt[threadIdx.x] = 0; }

__global__ void hist_kernel() {
    int i = blockIdx.x * blockDim.x + threadIdx.x;
    if (i < NN) atomicAdd(&g_cnt[g_seg[i]], 1);
}

__global__ void scan_kernel() {
    __shared__ int sh[CK];
    int t = threadIdx.x;
    int v = g_cnt[t];
    sh[t] = v;
    __syncthreads();
    for (int o = 1; o < CK; o <<= 1) {
        int u = (t >= o) ? sh[t - o] : 0;
        __syncthreads();
        sh[t] += u;
        __syncthreads();
    }
    g_off[t] = sh[t] - v;   // exclusive
    g_cur[t] = 0;
}

__global__ void scatter_kernel() {
    int i = blockIdx.x * blockDim.x + threadIdx.x;
    if (i < NN) {
        int sg = g_seg[i];
        int p = atomicAdd(&g_cur[sg], 1);
        g_order[g_off[sg] + p] = i;
    }
}

// block s sums its rows and writes mean (sum / max(cnt,1))
__global__ void gather_mean_kernel(const float* __restrict__ X) {
    __shared__ int sidx[256];
    const int sg = blockIdx.x, t = threadIdx.x;
    const int n = g_cnt[sg], off = g_off[sg];
    float ax = 0.f, ay = 0.f;
    for (int base = 0; base < n; base += 256) {
        int m = min(256, n - base);
        __syncthreads();
        if (t < m) sidx[t] = g_order[off + base + t];
        __syncthreads();
        for (int j = 0; j < m; j++) {
            float2 v = *(const float2*)&X[(size_t)sidx[j] * DD + 2 * t];
            ax += v.x; ay += v.y;
        }
    }
    float inv = 1.0f / (float)max(n, 1);
    g_means[(size_t)sg * DD + 2 * t]     = ax * inv;
    g_means[(size_t)sg * DD + 2 * t + 1] = ay * inv;
}

// ---------------- generic tiled SGEMM: C = A[M,K]@B[K,N] + bias ----------------
__launch_bounds__(256)
__global__ void sgemm_kernel(const float* __restrict__ A, const float* __restrict__ B,
                             const float* __restrict__ bias, float* __restrict__ Cout,
                             int M, int Np, int Kp)
{
    __shared__ float As[2][16][68];
    __shared__ float Bs[2][16][64];
    const int tid = threadIdx.x;
    const int ty = tid >> 4, tx = tid & 15;
    const int row0 = blockIdx.x * 64, col0 = blockIdx.y * 64;
    const int arow = tid >> 2, ak = (tid & 3) << 2;
    const int bk = tid >> 4, bn = (tid & 15) << 2;

    const float* Aptr = A + (size_t)(row0 + arow) * Kp + ak;
    const float* Bptr = B + (size_t)bk * Np + col0 + bn;

    float acc[4][4];
#pragma unroll
    for (int i = 0; i < 4; i++)
#pragma unroll
        for (int j = 0; j < 4; j++) acc[i][j] = 0.f;

    {
        float4 a = *(const float4*)Aptr;
        As[0][ak + 0][arow] = a.x; As[0][ak + 1][arow] = a.y;
        As[0][ak + 2][arow] = a.z; As[0][ak + 3][arow] = a.w;
        *(float4*)&Bs[0][bk][bn] = *(const float4*)Bptr;
    }
    __syncthreads();

    int buf = 0;
    for (int k0 = 0; k0 < Kp; k0 += 16) {
        const bool nxt = (k0 + 16) < Kp;
        float4 pa, pb;
        if (nxt) {
            pa = *(const float4*)(Aptr + k0 + 16);
            pb = *(const float4*)(Bptr + (size_t)(k0 + 16) * Np);
        }
#pragma unroll
        for (int kk = 0; kk < 16; kk++) {
            float a4[4], b4[4];
            *(float4*)a4 = *(const float4*)&As[buf][kk][ty * 4];
            *(float4*)b4 = *(const float4*)&Bs[buf][kk][tx * 4];
#pragma unroll
            for (int i = 0; i < 4; i++)
#pragma unroll
                for (int j = 0; j < 4; j++) acc[i][j] += a4[i] * b4[j];
        }
        if (nxt) {
            int nb = buf ^ 1;
            As[nb][ak + 0][arow] = pa.x; As[nb][ak + 1][arow] = pa.y;
            As[nb][ak + 2][arow] = pa.z; As[nb][ak + 3][arow] = pa.w;
            *(float4*)&Bs[nb][bk][bn] = pb;
            __syncthreads();
            buf = nb;
        }
    }
#pragma unroll
    for (int i = 0; i < 4; i++)
#pragma unroll
        for (int j = 0; j < 4; j++) {
            int r = row0 + ty * 4 + i, c = col0 + tx * 4 + j;
            Cout[(size_t)r * Np + c] = acc[i][j] + bias[c];
        }
}

// ---------------- LayerNorm + ReLU in place on g_h (block per row) ----------------
__global__ void ln_relu_kernel(const float* __restrict__ gamma, const float* __restrict__ beta)
{
    __shared__ float sh[8];
    const int rowi = blockIdx.x;
    float* x = &g_h[(size_t)rowi * DD];
    const int t = threadIdx.x, lane = t & 31, w = t >> 5;
    float v0 = x[t], v1 = x[t + 256];

    float s = v0 + v1;
#pragma unroll
    for (int o = 16; o > 0; o >>= 1) s += __shfl_xor_sync(0xffffffffu, s, o);
    if (lane == 0) sh[w] = s;
    __syncthreads();
    if (t == 0) { float r = 0; for (int i = 0; i < 8; i++) r += sh[i]; sh[0] = r; }
    __syncthreads();
    float mean = sh[0] * (1.f / 512.f);
    __syncthreads();

    float d0 = v0 - mean, d1 = v1 - mean;
    float q = d0 * d0 + d1 * d1;
#pragma unroll
    for (int o = 16; o > 0; o >>= 1) q += __shfl_xor_sync(0xffffffffu, q, o);
    if (lane == 0) sh[w] = q;
    __syncthreads();
    if (t == 0) { float r = 0; for (int i = 0; i < 8; i++) r += sh[i]; sh[0] = r; }
    __syncthreads();
    float inv = rsqrtf(sh[0] * (1.f / 512.f) + 1e-5f);

    x[t]       = fmaxf(d0 * inv * gamma[t] + beta[t], 0.f);
    x[t + 256] = fmaxf(d1 * inv * gamma[t + 256] + beta[t + 256], 0.f);
}

// ---------------- lp = masked mean of refined over non-empty clusters ----------------
__global__ void lp_kernel(int l)
{
    const int c = blockIdx.x, d = threadIdx.x;
    float s = 0.f, ne = 0.f;
#pragma unroll
    for (int k = 0; k < KK; k++) {
        int sgi = c * KK + k;
        if (g_cnt[sgi] > 0) { s += g_ref[(size_t)sgi * DD + d]; ne += 1.f; }
    }
    float v = s / ne;
    g_lp[(size_t)c * DD + d] = v;
    g_comb[(size_t)c * (LL * DD) + l * DD + d] = v;
}

// ---------------- current = src + lp[label] ----------------
__global__ void update_kernel(const float* __restrict__ src, const int* __restrict__ labels)
{
    size_t idx = (size_t)blockIdx.x * blockDim.x + threadIdx.x;  // over N*128 float4
    int row = (int)(idx >> 7), q = (int)(idx & 127);
    float4 v = ((const float4*)src)[idx];
    int lab = __ldg(&labels[row]);
    float4 p = ((const float4*)g_lp)[(size_t)lab * 128 + q];
    v.x += p.x; v.y += p.y; v.z += p.z; v.w += p.w;
    ((float4*)g_current)[idx] = v;
}

// ---------------- small-M GEMM for the combiner: out[c, :512] ----------------
__global__ void smallm_kernel(const float* __restrict__ A, const float* __restrict__ B,
                              const float* __restrict__ bias, float* __restrict__ out,
                              int Kp, int relu)
{
    __shared__ float a_s[LL * DD];  // up to 1536
    const int c = blockIdx.x, t = threadIdx.x;
    for (int i = t; i < Kp; i += 512) a_s[i] = A[(size_t)c * Kp + i];
    __syncthreads();
    float acc = 0.f;
#pragma unroll 4
    for (int k = 0; k < Kp; k++) acc += a_s[k] * B[(size_t)k * DD + t];
    acc += bias[t];
    if (relu) acc = fmaxf(acc, 0.f);
    out[(size_t)c * DD + t] = acc;
}

// ---------------- host launcher ----------------
extern "C" void kernel_launch(void* const* d_in, const int* in_sizes, int n_in,
                              void* d_out, int out_size)
{
    const float* X0      = (const float*)d_in[0];
    const int*   labels  = (const int*)  d_in[1];
    const float* ch_w1   = (const float*)d_in[2];   // [3,512,256]
    const float* ch_b1   = (const float*)d_in[3];   // [3,256]
    const float* ch_w2   = (const float*)d_in[4];   // [3,256,16]
    const float* ch_b2   = (const float*)d_in[5];   // [3,16]
    const float* ref_w1  = (const float*)d_in[6];   // [3,512,512]
    const float* ref_b1  = (const float*)d_in[7];   // [3,512]
    const float* ln_g    = (const float*)d_in[8];   // [3,512]
    const float* ln_b    = (const float*)d_in[9];   // [3,512]
    const float* ref_w2  = (const float*)d_in[10];  // [3,512,512]
    const float* ref_b2  = (const float*)d_in[11];  // [3,512]
    const float* comb_w1 = (const float*)d_in[12];  // [1536,512]
    const float* comb_b1 = (const float*)d_in[13];  // [512]
    const float* comb_w2 = (const float*)d_in[14];  // [512,512]
    const float* comb_b2 = (const float*)d_in[15];  // [512]
    float* out = (float*)d_out;

    float* curp = nullptr;
    cudaGetSymbolAddress((void**)&curp, g_current);
    float* meansp = nullptr;
    cudaGetSymbolAddress((void**)&meansp, g_means);
    float* hp = nullptr;
    cudaGetSymbolAddress((void**)&hp, g_h);
    float* refp = nullptr;
    cudaGetSymbolAddress((void**)&refp, g_ref);
    float* combp = nullptr;
    cudaGetSymbolAddress((void**)&combp, g_comb);
    float* tp = nullptr;
    cudaGetSymbolAddress((void**)&tp, g_t);

    const float* X = X0;
    for (int l = 0; l < LL; l++) {
        assign_kernel<<<NN / 64, 256>>>(X,
                                        ch_w1 + (size_t)l * DD * HH,
                                        ch_b1 + (size_t)l * HH,
                                        ch_w2 + (size_t)l * HH * KK,
                                        ch_b2 + (size_t)l * KK,
                                        labels);
        zero_cnt_kernel<<<1, CK>>>();
        hist_kernel<<<NN / 256, 256>>>();
        scan_kernel<<<1, CK>>>();
        scatter_kernel<<<NN / 256, 256>>>();
        gather_mean_kernel<<<CK, 256>>>(X);

        sgemm_kernel<<<dim3(CK / 64, DD / 64), 256>>>(
            meansp, ref_w1 + (size_t)l * DD * DD, ref_b1 + (size_t)l * DD, hp,
            CK, DD, DD);
        ln_relu_kernel<<<CK, 256>>>(ln_g + (size_t)l * DD, ln_b + (size_t)l * DD);
        sgemm_kernel<<<dim3(CK / 64, DD / 64), 256>>>(
            hp, ref_w2 + (size_t)l * DD * DD, ref_b2 + (size_t)l * DD, refp,
            CK, DD, DD);
        lp_kernel<<<CC, DD>>>(l);

        if (l < LL - 1) {
            update_kernel<<<(NN * (DD / 4)) / 256, 256>>>(X, labels);
            X = curp;
        }
    }

    smallm_kernel<<<CC, DD>>>(combp, comb_w1, comb_b1, tp, LL * DD, 1);
    smallm_kernel<<<CC, DD>>>(tp, comb_w2, comb_b2, out, DD, 0);
}

// round 16
// speedup vs baseline: 1.0972x; 1.0972x over previous
#include <cuda_runtime.h>
#include <cstdint>

#define NN 65536
#define DD 512
#define HH 256
#define KK 16
#define LL 3
#define CC 64
#define CK 1024   // C*K

// ---------------- scratch (device globals; no allocations allowed) ----------------
__device__ float g_xhi[NN * DD];
__device__ float g_xlo[NN * DD];
__device__ float g_w1t_hi[LL * HH * DD];   // W1^T tf32-hi  [L][256][512]
__device__ float g_w1t_lo[LL * HH * DD];
__device__ float g_cum[CC * DD];           // accumulated lp offsets per class
__device__ float g_cumw[CC * HH];          // cum @ W1_l + b1
__device__ float g_plog[2 * NN * KK];      // partial logits, 2 N-slabs
__device__ int   g_seg[NN];
__device__ int   g_cnt[CK];
__device__ int   g_off[CK];
__device__ int   g_cur[CK];
__device__ int   g_order[NN];
__device__ float g_means[CK * DD];
__device__ float g_h[CK * DD];
__device__ float g_ref[CK * DD];
__device__ float g_lp[CC * DD];
__device__ float g_comb[CC * LL * DD];
__device__ float g_t[CC * DD];

// ---------------- PTX helpers (portable, no 'a' features) ----------------
__device__ __forceinline__ unsigned smem_u32(const void* p) {
    return (unsigned)__cvta_generic_to_shared(p);
}
__device__ __forceinline__ void cp16(unsigned dst, const void* src) {
    asm volatile("cp.async.cg.shared.global [%0], [%1], 16;\n" :: "r"(dst), "l"(src));
}
__device__ __forceinline__ void cp_commit() { asm volatile("cp.async.commit_group;\n"); }
__device__ __forceinline__ void cp_wait0()  { asm volatile("cp.async.wait_group 0;\n" ::: "memory"); }
__device__ __forceinline__ void cp_wait1()  { asm volatile("cp.async.wait_group 1;\n" ::: "memory"); }

__device__ __forceinline__ float to_tf32(float x) {
    float r; asm("cvt.rna.tf32.f32 %0, %1;" : "=f"(r) : "f"(x)); return r;
}
// m16n8k8 tf32 mma: A row-major (4 regs), B col-major (2 regs), C fp32 (4 regs)
__device__ __forceinline__ void mma_tf32(float* c,
                                         unsigned a0, unsigned a1, unsigned a2, unsigned a3,
                                         unsigned b0, unsigned b1) {
    asm volatile("mma.sync.aligned.m16n8k8.row.col.f32.tf32.tf32.f32 "
                 "{%0,%1,%2,%3}, {%4,%5,%6,%7}, {%8,%9}, {%0,%1,%2,%3};"
                 : "+f"(c[0]), "+f"(c[1]), "+f"(c[2]), "+f"(c[3])
                 : "r"(a0), "r"(a1), "r"(a2), "r"(a3), "r"(b0), "r"(b1));
}

// ---------------- one-time prep kernels ----------------
__global__ void splitx_kernel(const float* __restrict__ X) {
    size_t i = (size_t)blockIdx.x * 256 + threadIdx.x;   // over NN*DD/4 float4
    float4 v = ((const float4*)X)[i];
    float4 hi, lo;
    hi.x = to_tf32(v.x); lo.x = to_tf32(v.x - hi.x);
    hi.y = to_tf32(v.y); lo.y = to_tf32(v.y - hi.y);
    hi.z = to_tf32(v.z); lo.z = to_tf32(v.z - hi.z);
    hi.w = to_tf32(v.w); lo.w = to_tf32(v.w - hi.w);
    ((float4*)g_xhi)[i] = hi;
    ((float4*)g_xlo)[i] = lo;
}

// transpose W1 [L][512][256] -> W1^T hi/lo [L][256][512]
__global__ void wsplit_kernel(const float* __restrict__ w1) {
    __shared__ float tile[32][33];
    const int l = blockIdx.z;
    const int k0 = blockIdx.x * 32, n0 = blockIdx.y * 32;
    const int tx = threadIdx.x, ty = threadIdx.y;   // (32, 8)
#pragma unroll
    for (int i = 0; i < 4; i++)
        tile[ty + i * 8][tx] = w1[((size_t)l * DD + k0 + ty + i * 8) * HH + n0 + tx];
    __syncthreads();
#pragma unroll
    for (int i = 0; i < 4; i++) {
        float v = tile[tx][ty + i * 8];
        float h = to_tf32(v);
        size_t o = ((size_t)l * HH + n0 + ty + i * 8) * DD + k0 + tx;
        g_w1t_hi[o] = h;
        g_w1t_lo[o] = to_tf32(v - h);
    }
}

__global__ void zero_cum_kernel() {
    g_cum[blockIdx.x * 256 + threadIdx.x] = 0.f;
}

// cumw[c][h] = b1[h] + sum_k cum[c][k] * W1[k][h]
__global__ void cumw_kernel(const float* __restrict__ w1, const float* __restrict__ b1) {
    __shared__ float s[DD];
    const int c = blockIdx.x, t = threadIdx.x;   // 256 threads
    s[t] = g_cum[(size_t)c * DD + t];
    s[t + 256] = g_cum[(size_t)c * DD + t + 256];
    __syncthreads();
    float acc = b1[t];
#pragma unroll 8
    for (int k = 0; k < DD; k++) acc += s[k] * w1[(size_t)k * HH + t];
    g_cumw[(size_t)c * HH + t] = acc;
}

// ---------------- mma.sync 3xTF32 assign kernel ----------------
// grid (512, 2): 128 rows x 128-col N-half per CTA, K=512, Kc=16, 2-stage cp.async.
// smem: [0,8192) W2 slice [128][16]; stages at 8192 + st*40960:
//   A hi [128][20] (10240B) | A lo | B hi | B lo
#define AS_STRIDE 20
#define ST_BYTES  40960
#define SM_ST     8192
#define ASSIGN_SMEM (SM_ST + 2 * ST_BYTES)   // 90112

__launch_bounds__(256, 2)
__global__ void assign_mma_kernel(const float* __restrict__ xhi, const float* __restrict__ xlo,
                                  const float* __restrict__ whi, const float* __restrict__ wlo,
                                  const float* __restrict__ cumw,   // [64][256] incl b1
                                  const float* __restrict__ W2,     // [256][16]
                                  const int*   __restrict__ labels)
{
    extern __shared__ __align__(16) char smem[];
    float* W2s = (float*)smem;
    const int tid = threadIdx.x;
    const int wm = tid >> 5, lane = tid & 31;
    const int row0 = blockIdx.x * 128;
    const int n0 = blockIdx.y * 128;

    // stage W2 slice [n0..n0+127][16]
    {
        const float4* src = (const float4*)(W2 + (size_t)n0 * KK);
        float4* dst = (float4*)W2s;
        dst[tid] = src[tid];
        dst[tid + 256] = src[tid + 256];
    }

    auto load_chunk = [&](int c, int st) {
        unsigned ab = smem_u32(smem + SM_ST + st * ST_BYTES);
        unsigned bb = ab + 20480u;
#pragma unroll
        for (int i = 0; i < 4; i++) {
            int u = tid + i * 256;
            int sp = u >> 9, r = (u >> 2) & 127, q = u & 3;
            const float* s = (sp ? xlo : xhi) + (size_t)(row0 + r) * DD + c * 16 + q * 4;
            cp16(ab + (unsigned)sp * 10240u + (unsigned)r * 80u + (unsigned)q * 16u, s);
        }
#pragma unroll
        for (int i = 0; i < 4; i++) {
            int u = tid + i * 256;
            int sp = u >> 9, r = (u >> 2) & 127, q = u & 3;
            const float* s = (sp ? wlo : whi) + (size_t)(n0 + r) * DD + c * 16 + q * 4;
            cp16(bb + (unsigned)sp * 10240u + (unsigned)r * 80u + (unsigned)q * 16u, s);
        }
        cp_commit();
    };

    float acc[16][4];
#pragma unroll
    for (int nt = 0; nt < 16; nt++)
#pragma unroll
        for (int j = 0; j < 4; j++) acc[nt][j] = 0.f;

    const int r = lane >> 2, qk = lane & 3;

    load_chunk(0, 0);
    load_chunk(1, 1);

    for (int c = 0; c < 32; c++) {
        const int st = c & 1;
        if (c == 31) cp_wait0(); else cp_wait1();
        __syncthreads();

        const float* As  = (const float*)(smem + SM_ST + st * ST_BYTES);
        const float* Asl = As + 2560;
        const float* Bs  = As + 5120;
        const float* Bsl = As + 7680;
#pragma unroll
        for (int s = 0; s < 2; s++) {
            const int ka = qk + s * 8;
            const int ar0 = (wm * 16 + r) * AS_STRIDE + ka;
            const int ar1 = (wm * 16 + r + 8) * AS_STRIDE + ka;
            unsigned ah0 = __float_as_uint(As[ar0]);
            unsigned ah1 = __float_as_uint(As[ar1]);
            unsigned ah2 = __float_as_uint(As[ar0 + 4]);
            unsigned ah3 = __float_as_uint(As[ar1 + 4]);
            unsigned al0 = __float_as_uint(Asl[ar0]);
            unsigned al1 = __float_as_uint(Asl[ar1]);
            unsigned al2 = __float_as_uint(Asl[ar0 + 4]);
            unsigned al3 = __float_as_uint(Asl[ar1 + 4]);
#pragma unroll
            for (int nt = 0; nt < 16; nt++) {
                const int bo = (nt * 8 + r) * AS_STRIDE + ka;
                unsigned bh0 = __float_as_uint(Bs[bo]);
                unsigned bh1 = __float_as_uint(Bs[bo + 4]);
                unsigned bl0 = __float_as_uint(Bsl[bo]);
                unsigned bl1 = __float_as_uint(Bsl[bo + 4]);
                mma_tf32(acc[nt], ah0, ah1, ah2, ah3, bh0, bh1);
                mma_tf32(acc[nt], ah0, ah1, ah2, ah3, bl0, bl1);
                mma_tf32(acc[nt], al0, al1, al2, al3, bh0, bh1);
            }
        }
        __syncthreads();
        if (c + 2 < 32) load_chunk(c + 2, st);
    }

    // ---- epilogue: h = relu(acc + cumw[label]); partial logits over this N-half ----
    const int rowA = row0 + wm * 16 + r;
    const int rowB = rowA + 8;
    const int labA = labels[rowA], labB = labels[rowB];
    const float* cwA = cumw + (size_t)labA * HH + n0;
    const float* cwB = cumw + (size_t)labB * HH + n0;

    float lgA[16], lgB[16];
#pragma unroll
    for (int j = 0; j < 16; j++) { lgA[j] = 0.f; lgB[j] = 0.f; }

#pragma unroll
    for (int nt = 0; nt < 16; nt++) {
        const int cl = nt * 8 + qk * 2;
        float hA0 = fmaxf(acc[nt][0] + cwA[cl],     0.f);
        float hA1 = fmaxf(acc[nt][1] + cwA[cl + 1], 0.f);
        float hB0 = fmaxf(acc[nt][2] + cwB[cl],     0.f);
        float hB1 = fmaxf(acc[nt][3] + cwB[cl + 1], 0.f);
        const float4* w0 = (const float4*)(W2s + (size_t)cl * KK);
        const float4* w1 = (const float4*)(W2s + (size_t)(cl + 1) * KK);
#pragma unroll
        for (int q = 0; q < 4; q++) {
            float4 a = w0[q], b = w1[q];
            lgA[q * 4 + 0] += hA0 * a.x + hA1 * b.x;
            lgA[q * 4 + 1] += hA0 * a.y + hA1 * b.y;
            lgA[q * 4 + 2] += hA0 * a.z + hA1 * b.z;
            lgA[q * 4 + 3] += hA0 * a.w + hA1 * b.w;
            lgB[q * 4 + 0] += hB0 * a.x + hB1 * b.x;
            lgB[q * 4 + 1] += hB0 * a.y + hB1 * b.y;
            lgB[q * 4 + 2] += hB0 * a.z + hB1 * b.z;
            lgB[q * 4 + 3] += hB0 * a.w + hB1 * b.w;
        }
    }
    // reduce across the 4 lanes of each quad (they hold disjoint col subsets)
#pragma unroll
    for (int off = 1; off <= 2; off <<= 1) {
#pragma unroll
        for (int j = 0; j < 16; j++) {
            lgA[j] += __shfl_xor_sync(0xffffffffu, lgA[j], off);
            lgB[j] += __shfl_xor_sync(0xffffffffu, lgB[j], off);
        }
    }
    if (qk == 0) {
        float4* dA = (float4*)(g_plog + ((size_t)blockIdx.y * NN + rowA) * KK);
        float4* dB = (float4*)(g_plog + ((size_t)blockIdx.y * NN + rowB) * KK);
#pragma unroll
        for (int q = 0; q < 4; q++) {
            dA[q] = make_float4(lgA[q * 4], lgA[q * 4 + 1], lgA[q * 4 + 2], lgA[q * 4 + 3]);
            dB[q] = make_float4(lgB[q * 4], lgB[q * 4 + 1], lgB[q * 4 + 2], lgB[q * 4 + 3]);
        }
    }
}

// combine the two N-half partial logits (fixed order), + b2, argmax -> seg
__global__ void argmax_kernel(const int* __restrict__ labels, const float* __restrict__ B2) {
    const int row = blockIdx.x * 256 + threadIdx.x;
    const float* p0 = g_plog + (size_t)row * KK;
    const float* p1 = g_plog + (size_t)(NN + row) * KK;
    float best = -3.402823466e38f; int bi = 0;
#pragma unroll
    for (int j = 0; j < KK; j++) {
        float v = p0[j] + p1[j] + B2[j];
        if (v > best) { best = v; bi = j; }
    }
    g_seg[row] = labels[row] * KK + bi;
}

// ---------------- segment machinery (counting sort) ----------------
__global__ void zero_cnt_kernel() { g_cnt[threadIdx.x] = 0; }

__global__ void hist_kernel() {
    int i = blockIdx.x * blockDim.x + threadIdx.x;
    if (i < NN) atomicAdd(&g_cnt[g_seg[i]], 1);
}

__global__ void scan_kernel() {
    __shared__ int sh[CK];
    int t = threadIdx.x;
    int v = g_cnt[t];
    sh[t] = v;
    __syncthreads();
    for (int o = 1; o < CK; o <<= 1) {
        int u = (t >= o) ? sh[t - o] : 0;
        __syncthreads();
        sh[t] += u;
        __syncthreads();
    }
    g_off[t] = sh[t] - v;   // exclusive
    g_cur[t] = 0;
}

__global__ void scatter_kernel() {
    int i = blockIdx.x * blockDim.x + threadIdx.x;
    if (i < NN) {
        int sg = g_seg[i];
        int p = atomicAdd(&g_cur[sg], 1);
        g_order[g_off[sg] + p] = i;
    }
}

// block s: mean of X rows in segment + cum[class]  (current = X + cum[label])
__global__ void gather_mean_kernel(const float* __restrict__ X) {
    __shared__ int sidx[256];
    const int sg = blockIdx.x, t = threadIdx.x;
    const int n = g_cnt[sg], off = g_off[sg];
    float ax = 0.f, ay = 0.f;
    for (int base = 0; base < n; base += 256) {
        int m = min(256, n - base);
        __syncthreads();
        if (t < m) sidx[t] = g_order[off + base + t];
        __syncthreads();
        for (int j = 0; j < m; j++) {
            float2 v = *(const float2*)&X[(size_t)sidx[j] * DD + 2 * t];
            ax += v.x; ay += v.y;
        }
    }
    float inv = 1.0f / (float)max(n, 1);
    const int cls = sg >> 4;
    float cx = g_cum[(size_t)cls * DD + 2 * t];
    float cy = g_cum[(size_t)cls * DD + 2 * t + 1];
    g_means[(size_t)sg * DD + 2 * t]     = ax * inv + cx;
    g_means[(size_t)sg * DD + 2 * t + 1] = ay * inv + cy;
}

// ---------------- generic tiled SGEMM: C = A[M,K]@B[K,N] + bias ----------------
__launch_bounds__(256)
__global__ void sgemm_kernel(const float* __restrict__ A, const float* __restrict__ B,
                             const float* __restrict__ bias, float* __restrict__ Cout,
                             int M, int Np, int Kp)
{
    __shared__ float As[2][16][68];
    __shared__ float Bs[2][16][64];
    const int tid = threadIdx.x;
    const int ty = tid >> 4, tx = tid & 15;
    const int row0 = blockIdx.x * 64, col0 = blockIdx.y * 64;
    const int arow = tid >> 2, ak = (tid & 3) << 2;
    const int bk = tid >> 4, bn = (tid & 15) << 2;

    const float* Aptr = A + (size_t)(row0 + arow) * Kp + ak;
    const float* Bptr = B + (size_t)bk * Np + col0 + bn;

    float acc[4][4];
#pragma unroll
    for (int i = 0; i < 4; i++)
#pragma unroll
        for (int j = 0; j < 4; j++) acc[i][j] = 0.f;

    {
        float4 a = *(const float4*)Aptr;
        As[0][ak + 0][arow] = a.x; As[0][ak + 1][arow] = a.y;
        As[0][ak + 2][arow] = a.z; As[0][ak + 3][arow] = a.w;
        *(float4*)&Bs[0][bk][bn] = *(const float4*)Bptr;
    }
    __syncthreads();

    int buf = 0;
    for (int k0 = 0; k0 < Kp; k0 += 16) {
        const bool nxt = (k0 + 16) < Kp;
        float4 pa, pb;
        if (nxt) {
            pa = *(const float4*)(Aptr + k0 + 16);
            pb = *(const float4*)(Bptr + (size_t)(k0 + 16) * Np);
        }
#pragma unroll
        for (int kk = 0; kk < 16; kk++) {
            float a4[4], b4[4];
            *(float4*)a4 = *(const float4*)&As[buf][kk][ty * 4];
            *(float4*)b4 = *(const float4*)&Bs[buf][kk][tx * 4];
#pragma unroll
            for (int i = 0; i < 4; i++)
#pragma unroll
                for (int j = 0; j < 4; j++) acc[i][j] += a4[i] * b4[j];
        }
        if (nxt) {
            int nb = buf ^ 1;
            As[nb][ak + 0][arow] = pa.x; As[nb][ak + 1][arow] = pa.y;
            As[nb][ak + 2][arow] = pa.z; As[nb][ak + 3][arow] = pa.w;
            *(float4*)&Bs[nb][bk][bn] = pb;
            __syncthreads();
            buf = nb;
        }
    }
#pragma unroll
    for (int i = 0; i < 4; i++)
#pragma unroll
        for (int j = 0; j < 4; j++) {
            int rr = row0 + ty * 4 + i, cc = col0 + tx * 4 + j;
            Cout[(size_t)rr * Np + cc] = acc[i][j] + bias[cc];
        }
}

// ---------------- LayerNorm + ReLU in place on g_h (block per row) ----------------
__global__ void ln_relu_kernel(const float* __restrict__ gamma, const float* __restrict__ beta)
{
    __shared__ float sh[8];
    const int rowi = blockIdx.x;
    float* x = &g_h[(size_t)rowi * DD];
    const int t = threadIdx.x, lane = t & 31, w = t >> 5;
    float v0 = x[t], v1 = x[t + 256];

    float s = v0 + v1;
#pragma unroll
    for (int o = 16; o > 0; o >>= 1) s += __shfl_xor_sync(0xffffffffu, s, o);
    if (lane == 0) sh[w] = s;
    __syncthreads();
    if (t == 0) { float rr = 0; for (int i = 0; i < 8; i++) rr += sh[i]; sh[0] = rr; }
    __syncthreads();
    float mean = sh[0] * (1.f / 512.f);
    __syncthreads();

    float d0 = v0 - mean, d1 = v1 - mean;
    float q = d0 * d0 + d1 * d1;
#pragma unroll
    for (int o = 16; o > 0; o >>= 1) q += __shfl_xor_sync(0xffffffffu, q, o);
    if (lane == 0) sh[w] = q;
    __syncthreads();
    if (t == 0) { float rr = 0; for (int i = 0; i < 8; i++) rr += sh[i]; sh[0] = rr; }
    __syncthreads();
    float inv = rsqrtf(sh[0] * (1.f / 512.f) + 1e-5f);

    x[t]       = fmaxf(d0 * inv * gamma[t] + beta[t], 0.f);
    x[t + 256] = fmaxf(d1 * inv * gamma[t + 256] + beta[t + 256], 0.f);
}

// ---------------- lp = masked mean over non-empty clusters; cum += lp ----------------
__global__ void lp_kernel(int l)
{
    const int c = blockIdx.x, d = threadIdx.x;
    float s = 0.f, ne = 0.f;
#pragma unroll
    for (int k = 0; k < KK; k++) {
        int sgi = c * KK + k;
        if (g_cnt[sgi] > 0) { s += g_ref[(size_t)sgi * DD + d]; ne += 1.f; }
    }
    float v = s / ne;
    g_lp[(size_t)c * DD + d] = v;
    g_comb[(size_t)c * (LL * DD) + l * DD + d] = v;
    g_cum[(size_t)c * DD + d] += v;
}

// ---------------- small-M GEMM for the combiner ----------------
__global__ void smallm_kernel(const float* __restrict__ A, const float* __restrict__ B,
                              const float* __restrict__ bias, float* __restrict__ out,
                              int Kp, int relu)
{
    __shared__ float a_s[LL * DD];
    const int c = blockIdx.x, t = threadIdx.x;
    for (int i = t; i < Kp; i += 512) a_s[i] = A[(size_t)c * Kp + i];
    __syncthreads();
    float acc = 0.f;
#pragma unroll 4
    for (int k = 0; k < Kp; k++) acc += a_s[k] * B[(size_t)k * DD + t];
    acc += bias[t];
    if (relu) acc = fmaxf(acc, 0.f);
    out[(size_t)c * DD + t] = acc;
}

// ---------------- host launcher ----------------
extern "C" void kernel_launch(void* const* d_in, const int* in_sizes, int n_in,
                              void* d_out, int out_size)
{
    const float* X0      = (const float*)d_in[0];
    const int*   labels  = (const int*)  d_in[1];
    const float* ch_w1   = (const float*)d_in[2];   // [3,512,256]
    const float* ch_b1   = (const float*)d_in[3];   // [3,256]
    const float* ch_w2   = (const float*)d_in[4];   // [3,256,16]
    const float* ch_b2   = (const float*)d_in[5];   // [3,16]
    const float* ref_w1  = (const float*)d_in[6];   // [3,512,512]
    const float* ref_b1  = (const float*)d_in[7];   // [3,512]
    const float* ln_g    = (const float*)d_in[8];   // [3,512]
    const float* ln_b    = (const float*)d_in[9];   // [3,512]
    const float* ref_w2  = (const float*)d_in[10];  // [3,512,512]
    const float* ref_b2  = (const float*)d_in[11];  // [3,512]
    const float* comb_w1 = (const float*)d_in[12];  // [1536,512]
    const float* comb_b1 = (const float*)d_in[13];  // [512]
    const float* comb_w2 = (const float*)d_in[14];  // [512,512]
    const float* comb_b2 = (const float*)d_in[15];  // [512]
    float* out = (float*)d_out;

    float *xhip, *xlop, *w1thip, *w1tlop, *cumwp, *meansp, *hp, *refp, *combp, *tp;
    cudaGetSymbolAddress((void**)&xhip,   g_xhi);
    cudaGetSymbolAddress((void**)&xlop,   g_xlo);
    cudaGetSymbolAddress((void**)&w1thip, g_w1t_hi);
    cudaGetSymbolAddress((void**)&w1tlop, g_w1t_lo);
    cudaGetSymbolAddress((void**)&cumwp,  g_cumw);
    cudaGetSymbolAddress((void**)&meansp, g_means);
    cudaGetSymbolAddress((void**)&hp,     g_h);
    cudaGetSymbolAddress((void**)&refp,   g_ref);
    cudaGetSymbolAddress((void**)&combp,  g_comb);
    cudaGetSymbolAddress((void**)&tp,     g_t);

    static int smem_set = 0;
    if (!smem_set) {
        cudaFuncSetAttribute(assign_mma_kernel,
                             cudaFuncAttributeMaxDynamicSharedMemorySize, ASSIGN_SMEM);
        smem_set = 1;
    }

    // one-time per call: split X, transpose+split W1 (all levels), zero cum
    splitx_kernel<<<NN * DD / 4 / 256, 256>>>(X0);
    wsplit_kernel<<<dim3(DD / 32, HH / 32, LL), dim3(32, 8)>>>(ch_w1);
    zero_cum_kernel<<<CC * DD / 256, 256>>>();

    for (int l = 0; l < LL; l++) {
        cumw_kernel<<<CC, 256>>>(ch_w1 + (size_t)l * DD * HH, ch_b1 + (size_t)l * HH);
        assign_mma_kernel<<<dim3(NN / 128, 2), 256, ASSIGN_SMEM>>>(
            xhip, xlop,
            w1thip + (size_t)l * HH * DD, w1tlop + (size_t)l * HH * DD,
            cumwp,
            ch_w2 + (size_t)l * HH * KK,
            labels);
        argmax_kernel<<<NN / 256, 256>>>(labels, ch_b2 + (size_t)l * KK);

        zero_cnt_kernel<<<1, CK>>>();
        hist_kernel<<<NN / 256, 256>>>();
        scan_kernel<<<1, CK>>>();
        scatter_kernel<<<NN / 256, 256>>>();
        gather_mean_kernel<<<CK, 256>>>(X0);

        sgemm_kernel<<<dim3(CK / 64, DD / 64), 256>>>(
            meansp, ref_w1 + (size_t)l * DD * DD, ref_b1 + (size_t)l * DD, hp,
            CK, DD, DD);
        ln_relu_kernel<<<CK, 256>>>(ln_g + (size_t)l * DD, ln_b + (size_t)l * DD);
        sgemm_kernel<<<dim3(CK / 64, DD / 64), 256>>>(
            hp, ref_w2 + (size_t)l * DD * DD, ref_b2 + (size_t)l * DD, refp,
            CK, DD, DD);
        lp_kernel<<<CC, DD>>>(l);
    }

    smallm_kernel<<<CC, DD>>>(combp, comb_w1, comb_b1, tp, LL * DD, 1);
    smallm_kernel<<<CC, DD>>>(tp, comb_w2, comb_b2, out, DD, 0);
}